// round 14
// baseline (speedup 1.0000x reference)
#include <cuda_runtime.h>

#define NPTS      8192
#define THREADS   256
#define WPC       8
#define R         8
#define NC        (R / 2)
#define ICHUNK    256
#define IBLKS     (NPTS / ICHUNK)        // 32
#define JTILE     32
#define JBLKS     (NPTS / JTILE)         // 256
#define JGROUP    8
#define RECT_P    (IBLKS / 2)            // 16
#define RECT_C    (IBLKS + 1)            // 33
#define TPT_SYM   (RECT_P * RECT_C * JGROUP)  // 4224
#define TPT_FULL  (IBLKS * JBLKS)             // 8192
#define NTASKS    (2 * TPT_SYM + TPT_FULL)    // 16640
#define GRID      592
#define PREP_CTAS 32
#define NCELL     1024                   // 32x32 morton cells
#define CPC       (NCELL / PREP_CTAS)    // 32 cells zeroed per prep CTA
#define CUT       40.0f                  // drop pairs with k < 2^-40
#define LOG2E_F   1.4426950408889634f
#define FULLMASK  0xFFFFFFFFu

typedef unsigned long long ull;

__device__ __forceinline__ float ex2_approx(float x) {
    float r;
    asm("ex2.approx.ftz.f32 %0, %1;" : "=f"(r) : "f"(x));
    return r;
}
__device__ __forceinline__ ull pack2(float lo, float hi) {
    ull p;
    asm("mov.b64 %0, {%1, %2};" : "=l"(p) : "f"(lo), "f"(hi));
    return p;
}
__device__ __forceinline__ unsigned int ld_acq(unsigned int* p) {
    unsigned int v;
    asm volatile("ld.acquire.gpu.u32 %0, [%1];" : "=r"(v) : "l"(p));
    return v;
}
__device__ __forceinline__ void st_rel(unsigned int* p, unsigned int v) {
    asm volatile("st.release.gpu.global.u32 [%0], %1;" :: "l"(p), "r"(v) : "memory");
}
__device__ __forceinline__ void arrive_rel(unsigned int* p) {
    asm volatile("red.release.gpu.global.add.u32 [%0], 1;" :: "l"(p) : "memory");
}
__device__ __forceinline__ unsigned int part1by1(unsigned int v) {
    v &= 0x0000FFFFu;
    v = (v | (v << 8)) & 0x00FF00FFu;
    v = (v | (v << 4)) & 0x0F0F0F0Fu;
    v = (v | (v << 2)) & 0x33333333u;
    v = (v | (v << 1)) & 0x55555555u;
    return v;
}
__device__ __forceinline__ float warp_min(float v) {
    for (int o = 16; o; o >>= 1) v = fminf(v, __shfl_xor_sync(FULLMASK, v, o));
    return v;
}
__device__ __forceinline__ float warp_max(float v) {
    for (int o = 16; o; o >>= 1) v = fmaxf(v, __shfl_xor_sync(FULLMASK, v, o));
    return v;
}

// Scratch (no allocations allowed)
__device__ float2 g_cb[NPTS], g_ct[NPTS];      // scaled (NOT centered), unsorted
__device__ int    g_cellb[NPTS], g_cellt[NPTS];
__device__ float2 g_sb[NPTS], g_st[NPTS];      // morton-sorted
__device__ unsigned int g_histb[NCELL], g_histt[NCELL];
__device__ unsigned int g_curb[NCELL],  g_curt[NCELL];
__device__ float4 g_iboxb[IBLKS], g_iboxt[IBLKS];  // (xlo,xhi,ylo,yhi)
__device__ float4 g_jboxb[JBLKS], g_jboxt[JBLKS];
__device__ double g_mean[2];
__device__ float  g_delta[2];
__device__ double g_sum[3];
__device__ unsigned int g_barZ, g_barB, g_barD, g_barE, g_barDel;
__device__ unsigned int g_flagC, g_flagDel;
__device__ unsigned int g_task, g_done;

__device__ __forceinline__ void block_reduce_add(double v, double* dst,
                                                 double* sred, int tid) {
    sred[tid] = v;
    __syncthreads();
    for (int s = THREADS / 2; s > 0; s >>= 1) {
        if (tid < s) sred[tid] += sred[tid + s];
        __syncthreads();
    }
    if (tid == 0) atomicAdd(dst, sred[0]);
    __syncthreads();
}
__device__ __forceinline__ float block_reduce_min(float v, float* sf, int tid) {
    sf[tid] = v;
    __syncthreads();
    for (int s = THREADS / 2; s > 0; s >>= 1) {
        if (tid < s) sf[tid] = fminf(sf[tid], sf[tid + s]);
        __syncthreads();
    }
    float r = sf[0];
    __syncthreads();
    return r;
}
__device__ __forceinline__ void prefix1024(unsigned int* hist, unsigned int* cur,
                                           unsigned int* ps, int tid) {
    unsigned int l0 = hist[tid * 4],     l1 = hist[tid * 4 + 1];
    unsigned int l2 = hist[tid * 4 + 2], l3 = hist[tid * 4 + 3];
    unsigned int tot = l0 + l1 + l2 + l3;
    ps[tid] = tot;
    __syncthreads();
    for (int off = 1; off < THREADS; off <<= 1) {
        unsigned int v = ps[tid];
        unsigned int u = (tid >= off) ? ps[tid - off] : 0u;
        __syncthreads();
        ps[tid] = v + u;
        __syncthreads();
    }
    unsigned int excl = ps[tid] - tot;
    cur[tid * 4] = excl; excl += l0;
    cur[tid * 4 + 1] = excl; excl += l1;
    cur[tid * 4 + 2] = excl; excl += l2;
    cur[tid * 4 + 3] = excl;
    __syncthreads();
}

#define MINIBAR(ctr) do {                                            \
    __threadfence();                                                 \
    __syncthreads();                                                 \
    if (tid == 0) {                                                  \
        arrive_rel(&(ctr));                                          \
        while (ld_acq(&(ctr)) < PREP_CTAS) { }                       \
    }                                                                \
    __syncthreads();                                                 \
} while (0)

// ---------------------------------------------------------------------------
// Single kernel.
//  Prep (CTAs 0..31): sort the SCALED (uncentered — kernel is shift
//  invariant) clouds by 32x32 Morton cell; bounding boxes per 256-pt
//  i-chunk and 32-pt j-tile. Delta = cb-ct reduced concurrently (only bt
//  needs it; bt tasks last). Pair phase (all CTAs, warp task queue,
//  triangle-pruned 2.031*N^2): task-level box-box skip, per-j compaction
//  into a dummy-padded tile, FIXED unroll-8 inner loop over ceil(nsurv/8)*8
//  slots (dummies have a=-1e30 -> exp2 -> +0). Pairs with c2*d^2 < -40
//  contribute < 2^-40 each: total perturbation ~1e-8 relative.
// ---------------------------------------------------------------------------
__global__ __launch_bounds__(THREADS, 4) void k_fused(
        const float* __restrict__ base, const float* __restrict__ tgt,
        const float* __restrict__ log_sigma, const float* __restrict__ log_scale,
        float* __restrict__ out) {
    __shared__ ull wtile[WPC][2][JTILE][4];
    __shared__ double sred[THREADS];
    __shared__ float sf[THREADS];
    __shared__ unsigned int ps[THREADS];
    __shared__ float4 s_jbb[JBLKS], s_jbt[JBLKS];
    __shared__ float4 s_ibb[IBLKS], s_ibt[IBLKS];

    const int tid  = threadIdx.x;
    const int wid  = tid >> 5;
    const int lane = tid & 31;
    const int cta  = blockIdx.x;

    const float s0 = expf(log_scale[0]);
    const float s1 = expf(log_scale[1]);
    const float sigma = expf(log_sigma[0]);
    const float c2 = -(1.0f / (2.0f * sigma * sigma)) * LOG2E_F;
    const float m  = -2.0f * c2;
    const float rc2 = CUT / (-c2);           // squared cutoff distance

    const float2* __restrict__ b2 = (const float2*)base;
    const float2* __restrict__ t2 = (const float2*)tgt;

    // ======================= PREP (32 CTAs) ===============================
    if (cta < PREP_CTAS) {
        const int i = cta * THREADS + tid;   // 0..8191

        // zero hist slice (visible after barZ)
        if (tid < CPC) {
            g_histb[cta * CPC + tid] = 0u;
            g_histt[cta * CPC + tid] = 0u;
        }

        float2 pb = b2[i];
        float2 pt = t2[i];
        const float bx = pb.x * s0, by = pb.y * s1;
        const float tx = pt.x * s0, ty = pt.y * s1;

        // delta reduction — non-blocking for the rest of the grid
        block_reduce_add((double)bx - (double)tx, &g_mean[0], sred, tid);
        block_reduce_add((double)by - (double)ty, &g_mean[1], sred, tid);
        if (tid == 0) {
            __threadfence();
            unsigned int d = atomicAdd(&g_barDel, 1u);
            if (d == PREP_CTAS - 1) {
                g_delta[0] = (float)(atomicAdd(&g_mean[0], 0.0) / (double)NPTS);
                g_delta[1] = (float)(atomicAdd(&g_mean[1], 0.0) / (double)NPTS);
                st_rel(&g_flagDel, 1u);
            }
        }
        MINIBAR(g_barZ);

        // cells + histogram (on raw scaled coords; clamp keeps it correct)
        g_cb[i] = make_float2(bx, by);
        g_ct[i] = make_float2(tx, ty);
        {
            int cx = min(max((int)((bx + 6.4f) * 2.5f), 0), 31);
            int cy = min(max((int)((by + 6.4f) * 2.5f), 0), 31);
            unsigned int cell = part1by1((unsigned)cx) | (part1by1((unsigned)cy) << 1);
            g_cellb[i] = (int)cell;
            atomicAdd(&g_histb[cell], 1u);
            cx = min(max((int)((tx + 6.4f) * 2.5f), 0), 31);
            cy = min(max((int)((ty + 6.4f) * 2.5f), 0), 31);
            cell = part1by1((unsigned)cx) | (part1by1((unsigned)cy) << 1);
            g_cellt[i] = (int)cell;
            atomicAdd(&g_histt[cell], 1u);
        }
        MINIBAR(g_barB);

        // prefix sums (CTA0 only)
        if (cta == 0) {
            prefix1024(g_histb, g_curb, ps, tid);
            prefix1024(g_histt, g_curt, ps, tid);
            __threadfence();
            __syncthreads();
            if (tid == 0) st_rel(&g_flagC, 1u);
        } else {
            if (tid == 0) { while (ld_acq(&g_flagC) == 0u) { } }
        }
        __syncthreads();

        // counting-sort scatter
        {
            unsigned int pos = atomicAdd(&g_curb[g_cellb[i]], 1u);
            g_sb[pos] = g_cb[i];
            pos = atomicAdd(&g_curt[g_cellt[i]], 1u);
            g_st[pos] = g_ct[i];
        }
        MINIBAR(g_barD);

        // bounding boxes
        {
            float2 p = g_sb[cta * THREADS + tid];
            float xmn = block_reduce_min(p.x, sf, tid);
            float xmx = -block_reduce_min(-p.x, sf, tid);
            float ymn = block_reduce_min(p.y, sf, tid);
            float ymx = -block_reduce_min(-p.y, sf, tid);
            if (tid == 0) g_iboxb[cta] = make_float4(xmn, xmx, ymn, ymx);
            p = g_st[cta * THREADS + tid];
            xmn = block_reduce_min(p.x, sf, tid);
            xmx = -block_reduce_min(-p.x, sf, tid);
            ymn = block_reduce_min(p.y, sf, tid);
            ymx = -block_reduce_min(-p.y, sf, tid);
            if (tid == 0) g_iboxt[cta] = make_float4(xmn, xmx, ymn, ymx);

            int jt0 = cta * WPC + wid;              // 0..255
            float2 q = g_sb[jt0 * JTILE + lane];
            float a = warp_min(q.x), b = warp_max(q.x);
            float c = warp_min(q.y), d = warp_max(q.y);
            if (lane == 0) g_jboxb[jt0] = make_float4(a, b, c, d);
            q = g_st[jt0 * JTILE + lane];
            a = warp_min(q.x); b = warp_max(q.x);
            c = warp_min(q.y); d = warp_max(q.y);
            if (lane == 0) g_jboxt[jt0] = make_float4(a, b, c, d);
        }
        __threadfence();
        __syncthreads();
        if (tid == 0) arrive_rel(&g_barE);
    }

    // ======================= global barrier ===============================
    if (tid == 0) { while (ld_acq(&g_barE) < PREP_CTAS) { } }
    __syncthreads();

    // boxes into smem
    for (int k = tid; k < JBLKS; k += THREADS) {
        s_jbb[k] = g_jboxb[k];
        s_jbt[k] = g_jboxt[k];
    }
    if (tid < IBLKS) {
        s_ibb[tid] = g_iboxb[tid];
        s_ibt[tid] = g_iboxt[tid];
    }
    __syncthreads();

    const unsigned int tbase =
        (unsigned int)__cvta_generic_to_shared(&wtile[wid][0][0][0]);

    // ======================= pair-task loop ===============================
    double abb = 0.0, att = 0.0, abt = 0.0;
    float dx = 0.0f, dy = 0.0f;
    bool have_delta = false;
    unsigned int buf = 0u;

    unsigned int tnext = 0u;
    if (lane == 0) tnext = atomicAdd(&g_task, 1u);
    unsigned int t = __shfl_sync(FULLMASK, tnext, 0);

    while (t < NTASKS) {
        if (lane == 0) tnext = atomicAdd(&g_task, 1u);

        // decode -> (type, it, jt, w)
        int type, it, jt;
        float w = 1.0f;
        if (t < 2u * TPT_SYM) {
            type = (t < TPT_SYM) ? 0 : 1;
            unsigned int rem = (t < TPT_SYM) ? t : t - TPT_SYM;
            unsigned int g   = rem >> 3;
            unsigned int sub = rem & 7u;
            unsigned int p = g / RECT_C;
            unsigned int c = g % RECT_C;
            unsigned int jg;
            if (c < (unsigned)(IBLKS - p)) { it = (int)p;               jg = p + c; }
            else                           { it = (int)(IBLKS - 1 - p); jg = c - 1; }
            if ((int)jg > it) w = 2.0f;
            jt = (int)(jg * JGROUP + sub);
        } else {
            type = 2;
            unsigned int rem = t - 2u * TPT_SYM;
            it = (int)(rem & (IBLKS - 1));
            jt = (int)(rem >> 5);
        }

        // bt gate: one-time per warp; delta long published by now
        if (type == 2 && !have_delta) {
            while (ld_acq(&g_flagDel) == 0u) { }
            dx = g_delta[0];
            dy = g_delta[1];
            have_delta = true;
        }
        const float jdx = (type == 2) ? dx : 0.0f;
        const float jdy = (type == 2) ? dy : 0.0f;

        const float4 ib = (type == 1) ? s_ibt[it] : s_ibb[it];
        float4 jb = (type == 0) ? s_jbb[jt] : s_jbt[jt];
        jb.x += jdx; jb.y += jdx; jb.z += jdy; jb.w += jdy;

        // task-level box-box distance test (warp-uniform)
        float ddx = fmaxf(fmaxf(ib.x - jb.y, jb.x - ib.y), 0.0f);
        float ddy = fmaxf(fmaxf(ib.z - jb.w, jb.z - ib.w), 0.0f);
        if (fmaf(ddx, ddx, ddy * ddy) <= rc2) {
            const float2* __restrict__ Ai = (type == 1) ? g_st : g_sb;
            const float2* __restrict__ Bj = (type == 0) ? g_sb : g_st;

            const unsigned int tb = tbase + buf * (JTILE * 32);

            // dummy prefill: a=-1e30 -> ex2 -> +0 (exact no-op pairs)
            {
                ull z  = 0ull;
                ull nn = pack2(-1e30f, -1e30f);
                unsigned int ta = tb + (unsigned)lane * 32;
                asm volatile("st.shared.v2.u64 [%0], {%1, %2};"
                             :: "r"(ta), "l"(z), "l"(z));
                asm volatile("st.shared.u64 [%0+16], %1;"
                             :: "r"(ta), "l"(nn));
            }
            __syncwarp();

            // per-j test vs i-chunk bbox + ballot compaction
            float2 q = Bj[jt * JTILE + lane];
            float qx = q.x + jdx, qy = q.y + jdy;
            float ax = fmaxf(fmaxf(ib.x - qx, qx - ib.y), 0.0f);
            float ay = fmaxf(fmaxf(ib.z - qy, qy - ib.w), 0.0f);
            bool keep = fmaf(ax, ax, ay * ay) <= rc2;
            unsigned int kmask = __ballot_sync(FULLMASK, keep);
            int nsurv = __popc(kmask);

            if (keep) {
                int pos = __popc(kmask & ((1u << lane) - 1u));
                float a = c2 * fmaf(qx, qx, qy * qy);
                ull uu = pack2(m * qx, m * qx);
                ull vv = pack2(m * qy, m * qy);
                ull aa = pack2(a, a);
                unsigned int ta = tb + (unsigned)pos * 32;
                asm volatile("st.shared.v2.u64 [%0], {%1, %2};"
                             :: "r"(ta), "l"(uu), "l"(vv));
                asm volatile("st.shared.u64 [%0+16], %1;"
                             :: "r"(ta), "l"(aa));
            }

            if (nsurv > 0) {
                // i-side, packed f32x2
                ull xii[NC], yii[NC], aii[NC];
                int i0 = it * ICHUNK + lane;
#pragma unroll
                for (int c = 0; c < NC; c++) {
                    float2 p0 = Ai[i0 + (2 * c)     * 32];
                    float2 p1 = Ai[i0 + (2 * c + 1) * 32];
                    float a0 = c2 * fmaf(p0.x, p0.x, p0.y * p0.y);
                    float a1 = c2 * fmaf(p1.x, p1.x, p1.y * p1.y);
                    xii[c] = pack2(p0.x, p1.x);
                    yii[c] = pack2(p0.y, p1.y);
                    aii[c] = pack2(a0, a1);
                }
                __syncwarp();

                float acc[R];
#pragma unroll
                for (int r = 0; r < R; r++) acc[r] = 0.0f;

                int jpad = (nsurv + 7) & ~7;        // fixed unroll-8 blocks
                unsigned int taddr = tb;
#pragma unroll 1
                for (int j0 = 0; j0 < jpad; j0 += 8) {
#pragma unroll
                    for (int u = 0; u < 8; u++) {
                        ull uu, vv, aa;
                        asm("ld.shared.v2.u64 {%0, %1}, [%2];"
                            : "=l"(uu), "=l"(vv) : "r"(taddr));
                        asm("ld.shared.u64 %0, [%1+16];"
                            : "=l"(aa) : "r"(taddr));
                        taddr += 32;
#pragma unroll
                        for (int c = 0; c < NC; c++) {
                            ull arg;
                            asm("add.rn.f32x2 %0, %1, %2;"
                                : "=l"(arg) : "l"(aii[c]), "l"(aa));
                            asm("fma.rn.f32x2 %0, %1, %2, %3;"
                                : "=l"(arg) : "l"(yii[c]), "l"(vv), "l"(arg));
                            asm("fma.rn.f32x2 %0, %1, %2, %3;"
                                : "=l"(arg) : "l"(xii[c]), "l"(uu), "l"(arg));
                            float lo, hi;
                            asm("mov.b64 {%0, %1}, %2;"
                                : "=f"(lo), "=f"(hi) : "l"(arg));
                            acc[2 * c]     += ex2_approx(lo);
                            acc[2 * c + 1] += ex2_approx(hi);
                        }
                    }
                }

                float s = ((acc[0] + acc[1]) + (acc[2] + acc[3])) +
                          ((acc[4] + acc[5]) + (acc[6] + acc[7]));
                double ws = (double)w * (double)s;
                if      (type == 0) abb += ws;
                else if (type == 1) att += ws;
                else                abt += ws;
            }
            buf ^= 1u;
        }

        t = __shfl_sync(FULLMASK, tnext, 0);
    }

    // ---- CTA-level reduction, then 3 atomics per CTA ----
    __syncthreads();
    block_reduce_add(abb, &g_sum[0], sred, tid);
    block_reduce_add(att, &g_sum[1], sred, tid);
    block_reduce_add(abt, &g_sum[2], sred, tid);

    // ---- finalize + full state reset (last CTA) ----
    if (tid == 0) {
        __threadfence();
        unsigned int d = atomicAdd(&g_done, 1u);
        if (d == (unsigned int)(GRID - 1)) {
            double sbb = atomicAdd(&g_sum[0], 0.0);
            double stt = atomicAdd(&g_sum[1], 0.0);
            double sbt = atomicAdd(&g_sum[2], 0.0);
            double inv = 1.0 / ((double)NPTS * (double)NPTS);
            out[0] = (float)((sbb + stt - 2.0 * sbt) * inv);
            g_sum[0] = 0.0; g_sum[1] = 0.0; g_sum[2] = 0.0;
            g_mean[0] = 0.0; g_mean[1] = 0.0;
            g_task = 0u; g_done = 0u;
            g_barZ = 0u; g_barB = 0u; g_barD = 0u; g_barE = 0u;
            g_barDel = 0u; g_flagC = 0u; g_flagDel = 0u;
            __threadfence();
        }
    }
}

// ---------------------------------------------------------------------------
extern "C" void kernel_launch(void* const* d_in, const int* in_sizes, int n_in,
                              void* d_out, int out_size) {
    const float* base = (const float*)d_in[0];
    const float* tgt  = (const float*)d_in[1];
    const float* lsig = (const float*)d_in[2];
    const float* lsc  = (const float*)d_in[3];

    k_fused<<<GRID, THREADS>>>(base, tgt, lsig, lsc, (float*)d_out);
}

// round 15
// speedup vs baseline: 1.0759x; 1.0759x over previous
#include <cuda_runtime.h>

#define NPTS      8192
#define THREADS   256
#define WPC       8
#define R         8
#define NC        (R / 2)
#define ICHUNK    256
#define IBLKS     (NPTS / ICHUNK)        // 32
#define JTILE     32
#define JBLKS     (NPTS / JTILE)         // 256
#define JGROUP    8
#define RECT_P    (IBLKS / 2)            // 16
#define RECT_C    (IBLKS + 1)            // 33
#define TPT_SYM   (RECT_P * RECT_C * JGROUP)  // 4224
#define TPT_FULL  (IBLKS * JBLKS)             // 8192
#define NTASKS    (2 * TPT_SYM + TPT_FULL)    // 16640
#define GRID      592
#define PREP_CTAS 32
#define NBIN      1024                   // x-sort bins
#define BPC       (NBIN / PREP_CTAS)     // 32 bins zeroed per prep CTA
#define CUT       40.0f                  // drop pairs with k < 2^-40
#define LOG2E_F   1.4426950408889634f
#define FULLMASK  0xFFFFFFFFu

typedef unsigned long long ull;

__device__ __forceinline__ float ex2_approx(float x) {
    float r;
    asm("ex2.approx.ftz.f32 %0, %1;" : "=f"(r) : "f"(x));
    return r;
}
__device__ __forceinline__ ull pack2(float lo, float hi) {
    ull p;
    asm("mov.b64 %0, {%1, %2};" : "=l"(p) : "f"(lo), "f"(hi));
    return p;
}
__device__ __forceinline__ unsigned int ld_acq(unsigned int* p) {
    unsigned int v;
    asm volatile("ld.acquire.gpu.u32 %0, [%1];" : "=r"(v) : "l"(p));
    return v;
}
__device__ __forceinline__ void st_rel(unsigned int* p, unsigned int v) {
    asm volatile("st.release.gpu.global.u32 [%0], %1;" :: "l"(p), "r"(v) : "memory");
}
__device__ __forceinline__ void arrive_rel(unsigned int* p) {
    asm volatile("red.release.gpu.global.add.u32 [%0], 1;" :: "l"(p) : "memory");
}

// Scratch (no allocations allowed)
__device__ float2 g_sb[NPTS], g_st[NPTS];      // scaled (uncentered), x-sorted
__device__ unsigned int g_histb[NBIN], g_histt[NBIN];
__device__ unsigned int g_curb[NBIN],  g_curt[NBIN];
__device__ double g_mean[2];
__device__ float  g_delta[2];
__device__ double g_sum[3];
__device__ unsigned int g_barZ, g_barB, g_barE, g_barDel;
__device__ unsigned int g_flagC, g_flagDel;
__device__ unsigned int g_task, g_done;

__device__ __forceinline__ void block_reduce_add(double v, double* dst,
                                                 double* sred, int tid) {
    sred[tid] = v;
    __syncthreads();
    for (int s = THREADS / 2; s > 0; s >>= 1) {
        if (tid < s) sred[tid] += sred[tid + s];
        __syncthreads();
    }
    if (tid == 0) atomicAdd(dst, sred[0]);
    __syncthreads();
}
__device__ __forceinline__ void prefix1024(unsigned int* hist, unsigned int* cur,
                                           unsigned int* ps, int tid) {
    unsigned int l0 = hist[tid * 4],     l1 = hist[tid * 4 + 1];
    unsigned int l2 = hist[tid * 4 + 2], l3 = hist[tid * 4 + 3];
    unsigned int tot = l0 + l1 + l2 + l3;
    ps[tid] = tot;
    __syncthreads();
    for (int off = 1; off < THREADS; off <<= 1) {
        unsigned int v = ps[tid];
        unsigned int u = (tid >= off) ? ps[tid - off] : 0u;
        __syncthreads();
        ps[tid] = v + u;
        __syncthreads();
    }
    unsigned int excl = ps[tid] - tot;
    cur[tid * 4] = excl; excl += l0;
    cur[tid * 4 + 1] = excl; excl += l1;
    cur[tid * 4 + 2] = excl; excl += l2;
    cur[tid * 4 + 3] = excl;
    __syncthreads();
}

#define SPIN(cond) do { while (cond) { __nanosleep(64); } } while (0)

#define MINIBAR(ctr) do {                                            \
    __threadfence();                                                 \
    __syncthreads();                                                 \
    if (tid == 0) {                                                  \
        arrive_rel(&(ctr));                                          \
        SPIN(ld_acq(&(ctr)) < PREP_CTAS);                            \
    }                                                                \
    __syncthreads();                                                 \
} while (0)

// ---------------------------------------------------------------------------
// Single kernel.
//  Prep (CTAs 0..31): 1-D counting sort of both scaled clouds by x (1024
//  bins). Kernel is shift-invariant so no centering; only bt needs
//  delta = cb-ct, reduced concurrently (non-blocking; bt tasks are last).
//  Pair phase (all 592 CTAs, warp task queue, triangle-pruned 2.031*N^2):
//  TASK-level 1-D interval test only — x-ranges of the sorted i-chunk /
//  j-tile are just endpoint reads. Surviving tasks run the full fixed-32
//  packed-f32x2 pipelined loop (R12 machinery, unchanged). Skipped pairs
//  have k < 2^-40 -> total perturbation ~1e-8 relative.
// ---------------------------------------------------------------------------
__global__ __launch_bounds__(THREADS, 4) void k_fused(
        const float* __restrict__ base, const float* __restrict__ tgt,
        const float* __restrict__ log_sigma, const float* __restrict__ log_scale,
        float* __restrict__ out) {
    __shared__ ull wtile[WPC][2][JTILE][4];   // (uu, vv, aa, pad) per j, x2 buf
    __shared__ double sred[THREADS];
    __shared__ unsigned int ps[THREADS];
    __shared__ float2 s_irb[IBLKS], s_irt[IBLKS];    // i-chunk x-range (lo,hi)
    __shared__ float2 s_jrb[JBLKS], s_jrt[JBLKS];    // j-tile  x-range (lo,hi)

    const int tid  = threadIdx.x;
    const int wid  = tid >> 5;
    const int lane = tid & 31;
    const int cta  = blockIdx.x;

    const float s0 = expf(log_scale[0]);
    const float s1 = expf(log_scale[1]);
    const float sigma = expf(log_sigma[0]);
    const float c2 = -(1.0f / (2.0f * sigma * sigma)) * LOG2E_F;
    const float m  = -2.0f * c2;
    const float rcut = sqrtf(CUT / (-c2));    // 1-D cutoff distance

    const float2* __restrict__ b2 = (const float2*)base;
    const float2* __restrict__ t2 = (const float2*)tgt;

    // ======================= PREP (32 CTAs): x counting sort ==============
    if (cta < PREP_CTAS) {
        const int i = cta * THREADS + tid;   // 0..8191

        if (tid < BPC) {
            g_histb[cta * BPC + tid] = 0u;
            g_histt[cta * BPC + tid] = 0u;
        }

        const float2 pb = b2[i];
        const float2 pt = t2[i];
        const float bx = pb.x * s0, by = pb.y * s1;
        const float tx = pt.x * s0, ty = pt.y * s1;

        // delta reduction — non-blocking for the rest of the grid
        block_reduce_add((double)bx - (double)tx, &g_mean[0], sred, tid);
        block_reduce_add((double)by - (double)ty, &g_mean[1], sred, tid);
        if (tid == 0) {
            __threadfence();
            unsigned int d = atomicAdd(&g_barDel, 1u);
            if (d == PREP_CTAS - 1) {
                g_delta[0] = (float)(atomicAdd(&g_mean[0], 0.0) / (double)NPTS);
                g_delta[1] = (float)(atomicAdd(&g_mean[1], 0.0) / (double)NPTS);
                st_rel(&g_flagDel, 1u);
            }
        }
        MINIBAR(g_barZ);          // hist zeroed everywhere

        const int binb = min(max((int)((bx + 6.4f) * 80.0f), 0), NBIN - 1);
        const int bint = min(max((int)((tx + 6.4f) * 80.0f), 0), NBIN - 1);
        atomicAdd(&g_histb[binb], 1u);
        atomicAdd(&g_histt[bint], 1u);
        MINIBAR(g_barB);          // all hist contributions in

        if (cta == 0) {
            prefix1024(g_histb, g_curb, ps, tid);
            prefix1024(g_histt, g_curt, ps, tid);
            __threadfence();
            __syncthreads();
            if (tid == 0) st_rel(&g_flagC, 1u);
        } else {
            if (tid == 0) SPIN(ld_acq(&g_flagC) == 0u);
        }
        __syncthreads();

        // scatter
        {
            unsigned int pos = atomicAdd(&g_curb[binb], 1u);
            g_sb[pos] = make_float2(bx, by);
            pos = atomicAdd(&g_curt[bint], 1u);
            g_st[pos] = make_float2(tx, ty);
        }
        __threadfence();
        __syncthreads();
        if (tid == 0) arrive_rel(&g_barE);
    }

    // ======================= global barrier ===============================
    if (tid == 0) SPIN(ld_acq(&g_barE) < PREP_CTAS);
    __syncthreads();

    // x-ranges: endpoints of sorted ranges (sorted by x -> lo/hi trivially)
    if (tid < IBLKS) {
        s_irb[tid] = make_float2(g_sb[tid * ICHUNK].x,
                                 g_sb[tid * ICHUNK + ICHUNK - 1].x);
        s_irt[tid] = make_float2(g_st[tid * ICHUNK].x,
                                 g_st[tid * ICHUNK + ICHUNK - 1].x);
    }
    {
        int k = tid;   // 0..255 = JBLKS
        s_jrb[k] = make_float2(g_sb[k * JTILE].x, g_sb[k * JTILE + JTILE - 1].x);
        s_jrt[k] = make_float2(g_st[k * JTILE].x, g_st[k * JTILE + JTILE - 1].x);
    }
    __syncthreads();

    const unsigned int tbase =
        (unsigned int)__cvta_generic_to_shared(&wtile[wid][0][0][0]);

    // ======================= pair-task loop ===============================
    double abb = 0.0, att = 0.0, abt = 0.0;
    float dx = 0.0f, dy = 0.0f;
    bool have_delta = false;
    unsigned int buf = 0u;

    unsigned int tnext = 0u;
    if (lane == 0) tnext = atomicAdd(&g_task, 1u);
    unsigned int t = __shfl_sync(FULLMASK, tnext, 0);

    while (t < NTASKS) {
        if (lane == 0) tnext = atomicAdd(&g_task, 1u);

        // decode -> (type, it, jt, w)
        int type, it, jt;
        float w = 1.0f;
        if (t < 2u * TPT_SYM) {
            type = (t < TPT_SYM) ? 0 : 1;
            unsigned int rem = (t < TPT_SYM) ? t : t - TPT_SYM;
            unsigned int g   = rem >> 3;
            unsigned int sub = rem & 7u;
            unsigned int p = g / RECT_C;
            unsigned int c = g % RECT_C;
            unsigned int jg;
            if (c < (unsigned)(IBLKS - p)) { it = (int)p;               jg = p + c; }
            else                           { it = (int)(IBLKS - 1 - p); jg = c - 1; }
            if ((int)jg > it) w = 2.0f;
            jt = (int)(jg * JGROUP + sub);
        } else {
            type = 2;
            unsigned int rem = t - 2u * TPT_SYM;
            it = (int)(rem & (IBLKS - 1));
            jt = (int)(rem >> 5);
        }

        // bt gate: one-time per warp; delta long published by now
        if (type == 2 && !have_delta) {
            SPIN(ld_acq(&g_flagDel) == 0u);
            dx = g_delta[0];
            dy = g_delta[1];
            have_delta = true;
        }
        const float jdx = (type == 2) ? dx : 0.0f;
        const float jdy = (type == 2) ? dy : 0.0f;

        // task-level 1-D interval test (warp-uniform, smem reads)
        const float2 ir = (type == 1) ? s_irt[it] : s_irb[it];
        float2 jr = (type == 0) ? s_jrb[jt] : s_jrt[jt];
        jr.x += jdx; jr.y += jdx;

        if (ir.x - jr.y <= rcut && jr.x - ir.y <= rcut) {
            const float2* __restrict__ Ai = (type == 1) ? g_st : g_sb;
            const float2* __restrict__ Bj = (type == 0) ? g_sb : g_st;

            // warp-private j-tile, double-buffered: (u,u)(v,v)(a,a)
            {
                float2 q = Bj[jt * JTILE + lane];
                float x = q.x + jdx;
                float y = q.y + jdy;
                float a = c2 * fmaf(x, x, y * y);
                ull uu = pack2(m * x, m * x);
                ull vv = pack2(m * y, m * y);
                ull aa = pack2(a, a);
                unsigned int ta = tbase + buf * (JTILE * 32) + lane * 32;
                asm volatile("st.shared.v2.u64 [%0], {%1, %2};"
                             :: "r"(ta), "l"(uu), "l"(vv));
                asm volatile("st.shared.u64 [%0+16], %1;"
                             :: "r"(ta), "l"(aa));
            }

            // i-side (pre-scaled), packed f32x2
            ull xii[NC], yii[NC], aii[NC];
            int i0 = it * ICHUNK + lane;
#pragma unroll
            for (int c = 0; c < NC; c++) {
                float2 p0 = Ai[i0 + (2 * c)     * 32];
                float2 p1 = Ai[i0 + (2 * c + 1) * 32];
                float a0 = c2 * fmaf(p0.x, p0.x, p0.y * p0.y);
                float a1 = c2 * fmaf(p1.x, p1.x, p1.y * p1.y);
                xii[c] = pack2(p0.x, p1.x);
                yii[c] = pack2(p0.y, p1.y);
                aii[c] = pack2(a0, a1);
            }

            __syncwarp();                   // tile visible to all lanes

            float acc[R];
#pragma unroll
            for (int r = 0; r < R; r++) acc[r] = 0.0f;

            unsigned int taddr = tbase + buf * (JTILE * 32);
#pragma unroll 4
            for (int j = 0; j < JTILE; j++) {
                ull uu, vv, aa;
                asm("ld.shared.v2.u64 {%0, %1}, [%2];"
                    : "=l"(uu), "=l"(vv) : "r"(taddr));
                asm("ld.shared.u64 %0, [%1+16];"
                    : "=l"(aa) : "r"(taddr));
                taddr += 32;
#pragma unroll
                for (int c = 0; c < NC; c++) {
                    ull arg;
                    asm("add.rn.f32x2 %0, %1, %2;"
                        : "=l"(arg) : "l"(aii[c]), "l"(aa));
                    asm("fma.rn.f32x2 %0, %1, %2, %3;"
                        : "=l"(arg) : "l"(yii[c]), "l"(vv), "l"(arg));
                    asm("fma.rn.f32x2 %0, %1, %2, %3;"
                        : "=l"(arg) : "l"(xii[c]), "l"(uu), "l"(arg));
                    float lo, hi;
                    asm("mov.b64 {%0, %1}, %2;" : "=f"(lo), "=f"(hi) : "l"(arg));
                    acc[2 * c]     += ex2_approx(lo);
                    acc[2 * c + 1] += ex2_approx(hi);
                }
            }

            float s = ((acc[0] + acc[1]) + (acc[2] + acc[3])) +
                      ((acc[4] + acc[5]) + (acc[6] + acc[7]));
            double ws = (double)w * (double)s;
            if      (type == 0) abb += ws;
            else if (type == 1) att += ws;
            else                abt += ws;

            buf ^= 1u;
        }

        t = __shfl_sync(FULLMASK, tnext, 0);
    }

    // ---- CTA-level reduction, then 3 atomics per CTA ----
    __syncthreads();
    block_reduce_add(abb, &g_sum[0], sred, tid);
    block_reduce_add(att, &g_sum[1], sred, tid);
    block_reduce_add(abt, &g_sum[2], sred, tid);

    // ---- finalize + full state reset (last CTA) ----
    if (tid == 0) {
        __threadfence();
        unsigned int d = atomicAdd(&g_done, 1u);
        if (d == (unsigned int)(GRID - 1)) {
            double sbb = atomicAdd(&g_sum[0], 0.0);
            double stt = atomicAdd(&g_sum[1], 0.0);
            double sbt = atomicAdd(&g_sum[2], 0.0);
            double inv = 1.0 / ((double)NPTS * (double)NPTS);
            out[0] = (float)((sbb + stt - 2.0 * sbt) * inv);
            g_sum[0] = 0.0; g_sum[1] = 0.0; g_sum[2] = 0.0;
            g_mean[0] = 0.0; g_mean[1] = 0.0;
            g_task = 0u; g_done = 0u;
            g_barZ = 0u; g_barB = 0u; g_barE = 0u; g_barDel = 0u;
            g_flagC = 0u; g_flagDel = 0u;
            __threadfence();
        }
    }
}

// ---------------------------------------------------------------------------
extern "C" void kernel_launch(void* const* d_in, const int* in_sizes, int n_in,
                              void* d_out, int out_size) {
    const float* base = (const float*)d_in[0];
    const float* tgt  = (const float*)d_in[1];
    const float* lsig = (const float*)d_in[2];
    const float* lsc  = (const float*)d_in[3];

    k_fused<<<GRID, THREADS>>>(base, tgt, lsig, lsc, (float*)d_out);
}

// round 16
// speedup vs baseline: 1.1695x; 1.0870x over previous
#include <cuda_runtime.h>

#define NPTS      8192
#define THREADS   256
#define WPC       8
#define R         8
#define NC        (R / 2)
#define ICHUNK    256
#define IBLKS     (NPTS / ICHUNK)        // 32
#define JTILE     32
#define JBLKS     (NPTS / JTILE)         // 256
#define JPB       (ICHUNK / JTILE)       // 8 j-tiles per i-chunk
#define NENTRY    96                     // 3 types x 32 i-chunks
#define GRID      592
#define PREP_CTAS 32
#define NBIN      1024
#define BPC       (NBIN / PREP_CTAS)
#define CUT       40.0f                  // drop pairs with k < 2^-40
#define EPS_SORT  0.03f                  // bin-granularity sort slack
#define LOG2E_F   1.4426950408889634f
#define FULLMASK  0xFFFFFFFFu

typedef unsigned long long ull;

__device__ __forceinline__ float ex2_approx(float x) {
    float r;
    asm("ex2.approx.ftz.f32 %0, %1;" : "=f"(r) : "f"(x));
    return r;
}
__device__ __forceinline__ ull pack2(float lo, float hi) {
    ull p;
    asm("mov.b64 %0, {%1, %2};" : "=l"(p) : "f"(lo), "f"(hi));
    return p;
}
__device__ __forceinline__ unsigned int ld_acq(unsigned int* p) {
    unsigned int v;
    asm volatile("ld.acquire.gpu.u32 %0, [%1];" : "=r"(v) : "l"(p));
    return v;
}
__device__ __forceinline__ void st_rel(unsigned int* p, unsigned int v) {
    asm volatile("st.release.gpu.global.u32 [%0], %1;" :: "l"(p), "r"(v) : "memory");
}
__device__ __forceinline__ void arrive_rel(unsigned int* p) {
    asm volatile("red.release.gpu.global.add.u32 [%0], 1;" :: "l"(p) : "memory");
}

// Scratch (no allocations allowed)
__device__ float2 g_sb[NPTS], g_st[NPTS];      // scaled (uncentered), x-sorted
__device__ unsigned int g_histb[NBIN], g_histt[NBIN];
__device__ unsigned int g_curb[NBIN],  g_curt[NBIN];
__device__ double g_mean[2];
__device__ float  g_delta[2];
__device__ double g_sum[3];
__device__ int    g_prefix[NENTRY + 1];
__device__ int    g_jstart[NENTRY];
__device__ unsigned int g_barZ, g_barB, g_barE, g_barDel;
__device__ unsigned int g_flagC, g_flagDel, g_flagT;
__device__ unsigned int g_task, g_done;

__device__ __forceinline__ void block_reduce_add(double v, double* dst,
                                                 double* sred, int tid) {
    sred[tid] = v;
    __syncthreads();
    for (int s = THREADS / 2; s > 0; s >>= 1) {
        if (tid < s) sred[tid] += sred[tid + s];
        __syncthreads();
    }
    if (tid == 0) atomicAdd(dst, sred[0]);
    __syncthreads();
}
__device__ __forceinline__ void prefix1024(unsigned int* hist, unsigned int* cur,
                                           unsigned int* ps, int tid) {
    unsigned int l0 = hist[tid * 4],     l1 = hist[tid * 4 + 1];
    unsigned int l2 = hist[tid * 4 + 2], l3 = hist[tid * 4 + 3];
    unsigned int tot = l0 + l1 + l2 + l3;
    ps[tid] = tot;
    __syncthreads();
    for (int off = 1; off < THREADS; off <<= 1) {
        unsigned int v = ps[tid];
        unsigned int u = (tid >= off) ? ps[tid - off] : 0u;
        __syncthreads();
        ps[tid] = v + u;
        __syncthreads();
    }
    unsigned int excl = ps[tid] - tot;
    cur[tid * 4] = excl; excl += l0;
    cur[tid * 4 + 1] = excl; excl += l1;
    cur[tid * 4 + 2] = excl; excl += l2;
    cur[tid * 4 + 3] = excl;
    __syncthreads();
}

#define SPIN(cond) do { while (cond) { __nanosleep(64); } } while (0)

#define MINIBAR(ctr) do {                                            \
    __threadfence();                                                 \
    __syncthreads();                                                 \
    if (tid == 0) {                                                  \
        arrive_rel(&(ctr));                                          \
        SPIN(ld_acq(&(ctr)) < PREP_CTAS);                            \
    }                                                                \
    __syncthreads();                                                 \
} while (0)

// last index in increasing arr[0..n-1] with arr[idx] <= V, or -1
__device__ __forceinline__ int upper_idx(const float* arr, int n, float V) {
    int lo = -1, hi = n - 1;
    while (lo < hi) {
        int mid = (lo + hi + 1) >> 1;
        if (arr[mid] <= V) lo = mid; else hi = mid - 1;
    }
    return lo;
}
// first index with arr[idx] >= V, or n
__device__ __forceinline__ int lower_idx(const float* arr, int n, float V) {
    int lo = 0, hi = n;
    while (lo < hi) {
        int mid = (lo + hi) >> 1;
        if (arr[mid] < V) lo = mid + 1; else hi = mid;
    }
    return lo;
}

// ---------------------------------------------------------------------------
// Single kernel.
//  Prep (CTAs 0..31): 1-D x counting sort (1024 bins) of both scaled clouds;
//  delta = cb-ct reduced concurrently (shift-invariance removes centering).
//  Table (CTA0): for each (type, i-chunk), the j-tiles within x-cutoff form a
//  CONTIGUOUS range [jstart, jend] (x-sorted) — 96 binary searches + prefix
//  sum -> dense task list with NO per-task tests and NO skips.
//  Pair phase (all 592 CTAs): warp pulls task-id, 7-step smem binary search
//  -> (type, it, jt); fixed-32 packed-f32x2 MUFU loop (R12 machinery).
//  Symmetry: sym types enumerate jt >= it*8 only; strictly-upper tiles get
//  x2 folded into the exponent (+1.0 in log2). Dropped pairs have
//  k < 2^-40 -> ~4e-9 relative perturbation.
// ---------------------------------------------------------------------------
__global__ __launch_bounds__(THREADS, 4) void k_fused(
        const float* __restrict__ base, const float* __restrict__ tgt,
        const float* __restrict__ log_sigma, const float* __restrict__ log_scale,
        float* __restrict__ out) {
    __shared__ ull wtile[WPC][2][JTILE][4];
    __shared__ double sred[THREADS];
    __shared__ unsigned int ps[THREADS];
    __shared__ float jxm_b[JBLKS], jxM_b[JBLKS], jxm_t[JBLKS], jxM_t[JBLKS];
    __shared__ int s_pref[NENTRY + 1];
    __shared__ int s_js[NENTRY];
    __shared__ float s_d[2];

    const int tid  = threadIdx.x;
    const int wid  = tid >> 5;
    const int lane = tid & 31;
    const int cta  = blockIdx.x;

    const float s0 = expf(log_scale[0]);
    const float s1 = expf(log_scale[1]);
    const float sigma = expf(log_sigma[0]);
    const float c2 = -(1.0f / (2.0f * sigma * sigma)) * LOG2E_F;
    const float m  = -2.0f * c2;
    const float rcut = sqrtf(CUT / (-c2)) + EPS_SORT;

    const float2* __restrict__ b2 = (const float2*)base;
    const float2* __restrict__ t2 = (const float2*)tgt;

    // ======================= PREP (32 CTAs): x counting sort ==============
    if (cta < PREP_CTAS) {
        const int i = cta * THREADS + tid;

        if (tid < BPC) {
            g_histb[cta * BPC + tid] = 0u;
            g_histt[cta * BPC + tid] = 0u;
        }

        const float2 pb = b2[i];
        const float2 pt = t2[i];
        const float bx = pb.x * s0, by = pb.y * s1;
        const float tx = pt.x * s0, ty = pt.y * s1;

        block_reduce_add((double)bx - (double)tx, &g_mean[0], sred, tid);
        block_reduce_add((double)by - (double)ty, &g_mean[1], sred, tid);
        if (tid == 0) {
            __threadfence();
            unsigned int d = atomicAdd(&g_barDel, 1u);
            if (d == PREP_CTAS - 1) {
                g_delta[0] = (float)(atomicAdd(&g_mean[0], 0.0) / (double)NPTS);
                g_delta[1] = (float)(atomicAdd(&g_mean[1], 0.0) / (double)NPTS);
                st_rel(&g_flagDel, 1u);
            }
        }
        MINIBAR(g_barZ);

        const int binb = min(max((int)((bx + 6.4f) * 80.0f), 0), NBIN - 1);
        const int bint = min(max((int)((tx + 6.4f) * 80.0f), 0), NBIN - 1);
        atomicAdd(&g_histb[binb], 1u);
        atomicAdd(&g_histt[bint], 1u);
        MINIBAR(g_barB);

        if (cta == 0) {
            prefix1024(g_histb, g_curb, ps, tid);
            prefix1024(g_histt, g_curt, ps, tid);
            __threadfence();
            __syncthreads();
            if (tid == 0) st_rel(&g_flagC, 1u);
        } else {
            if (tid == 0) SPIN(ld_acq(&g_flagC) == 0u);
        }
        __syncthreads();

        {
            unsigned int pos = atomicAdd(&g_curb[binb], 1u);
            g_sb[pos] = make_float2(bx, by);
            pos = atomicAdd(&g_curt[bint], 1u);
            g_st[pos] = make_float2(tx, ty);
        }
        MINIBAR(g_barE);

        // =================== TABLE (CTA0 only) ============================
        if (cta == 0) {
            if (tid == 0) SPIN(ld_acq(&g_flagDel) == 0u);
            __syncthreads();
            // j-tile x endpoints (sorted -> first/last element)
            jxm_b[tid] = g_sb[tid * JTILE].x;
            jxM_b[tid] = g_sb[tid * JTILE + JTILE - 1].x;
            jxm_t[tid] = g_st[tid * JTILE].x;
            jxM_t[tid] = g_st[tid * JTILE + JTILE - 1].x;
            __syncthreads();

            __shared__ int cnt[NENTRY];
            if (tid < NENTRY) {
                int type = tid >> 5, it = tid & 31;
                int jstart, jend;
                if (type == 0) {
                    float ihi = g_sb[it * ICHUNK + ICHUNK - 1].x;
                    jstart = it * JPB;
                    jend = upper_idx(jxm_b, JBLKS, ihi + rcut);
                } else if (type == 1) {
                    float ihi = g_st[it * ICHUNK + ICHUNK - 1].x;
                    jstart = it * JPB;
                    jend = upper_idx(jxm_t, JBLKS, ihi + rcut);
                } else {
                    float dxv = g_delta[0];
                    float ilo = g_sb[it * ICHUNK].x;
                    float ihi = g_sb[it * ICHUNK + ICHUNK - 1].x;
                    jstart = lower_idx(jxM_t, JBLKS, ilo - rcut - dxv);
                    jend   = upper_idx(jxm_t, JBLKS, ihi + rcut - dxv);
                }
                cnt[tid] = max(0, jend - jstart + 1);
                g_jstart[tid] = jstart;
            }
            __syncthreads();
            if (tid == 0) {
                int acc = 0;
                for (int e = 0; e < NENTRY; e++) {
                    g_prefix[e] = acc;
                    acc += cnt[e];
                }
                g_prefix[NENTRY] = acc;
                __threadfence();
                st_rel(&g_flagT, 1u);
            }
        }
    }

    // ======================= table gate + load ============================
    if (tid == 0) SPIN(ld_acq(&g_flagT) == 0u);
    __syncthreads();
    if (tid <= NENTRY) s_pref[tid] = g_prefix[tid];
    if (tid < NENTRY)  s_js[tid]   = g_jstart[tid];
    if (tid < 2)       s_d[tid]    = g_delta[tid];
    __syncthreads();

    const int ntasks = s_pref[NENTRY];
    const float dx = s_d[0], dy = s_d[1];
    const unsigned int tbase =
        (unsigned int)__cvta_generic_to_shared(&wtile[wid][0][0][0]);

    // ======================= pair-task loop (no skips) ====================
    double abb = 0.0, att = 0.0, abt = 0.0;
    unsigned int buf = 0u;

    unsigned int tnext = 0u;
    if (lane == 0) tnext = atomicAdd(&g_task, 1u);
    int t = (int)__shfl_sync(FULLMASK, tnext, 0);

    while (t < ntasks) {
        if (lane == 0) tnext = atomicAdd(&g_task, 1u);

        // decode: binary search prefix (warp-uniform, smem)
        int lo = 0, hi = NENTRY - 1;
        while (lo < hi) {
            int mid = (lo + hi + 1) >> 1;
            if (s_pref[mid] <= t) lo = mid; else hi = mid - 1;
        }
        const int e = lo;
        const int type = e >> 5;
        const int it = e & 31;
        const int jt = s_js[e] + (t - s_pref[e]);
        // symmetry weight x2 folded into exponent (+1 in log2)
        const float wadd = (type < 2 && jt >= (it + 1) * JPB) ? 1.0f : 0.0f;

        const float2* __restrict__ Ai = (type == 1) ? g_st : g_sb;
        const float2* __restrict__ Bj = (type == 0) ? g_sb : g_st;
        const float jdx = (type == 2) ? dx : 0.0f;
        const float jdy = (type == 2) ? dy : 0.0f;

        // warp-private j-tile, double-buffered: (u,u)(v,v)(a,a)
        {
            float2 q = Bj[jt * JTILE + lane];
            float x = q.x + jdx;
            float y = q.y + jdy;
            float a = c2 * fmaf(x, x, y * y) + wadd;
            ull uu = pack2(m * x, m * x);
            ull vv = pack2(m * y, m * y);
            ull aa = pack2(a, a);
            unsigned int ta = tbase + buf * (JTILE * 32) + lane * 32;
            asm volatile("st.shared.v2.u64 [%0], {%1, %2};"
                         :: "r"(ta), "l"(uu), "l"(vv));
            asm volatile("st.shared.u64 [%0+16], %1;"
                         :: "r"(ta), "l"(aa));
        }

        // i-side, packed f32x2
        ull xii[NC], yii[NC], aii[NC];
        int i0 = it * ICHUNK + lane;
#pragma unroll
        for (int c = 0; c < NC; c++) {
            float2 p0 = Ai[i0 + (2 * c)     * 32];
            float2 p1 = Ai[i0 + (2 * c + 1) * 32];
            float a0 = c2 * fmaf(p0.x, p0.x, p0.y * p0.y);
            float a1 = c2 * fmaf(p1.x, p1.x, p1.y * p1.y);
            xii[c] = pack2(p0.x, p1.x);
            yii[c] = pack2(p0.y, p1.y);
            aii[c] = pack2(a0, a1);
        }

        __syncwarp();

        float acc[R];
#pragma unroll
        for (int r = 0; r < R; r++) acc[r] = 0.0f;

        unsigned int taddr = tbase + buf * (JTILE * 32);
#pragma unroll 4
        for (int j = 0; j < JTILE; j++) {
            ull uu, vv, aa;
            asm("ld.shared.v2.u64 {%0, %1}, [%2];"
                : "=l"(uu), "=l"(vv) : "r"(taddr));
            asm("ld.shared.u64 %0, [%1+16];"
                : "=l"(aa) : "r"(taddr));
            taddr += 32;
#pragma unroll
            for (int c = 0; c < NC; c++) {
                ull arg;
                asm("add.rn.f32x2 %0, %1, %2;"
                    : "=l"(arg) : "l"(aii[c]), "l"(aa));
                asm("fma.rn.f32x2 %0, %1, %2, %3;"
                    : "=l"(arg) : "l"(yii[c]), "l"(vv), "l"(arg));
                asm("fma.rn.f32x2 %0, %1, %2, %3;"
                    : "=l"(arg) : "l"(xii[c]), "l"(uu), "l"(arg));
                float flo, fhi;
                asm("mov.b64 {%0, %1}, %2;" : "=f"(flo), "=f"(fhi) : "l"(arg));
                acc[2 * c]     += ex2_approx(flo);
                acc[2 * c + 1] += ex2_approx(fhi);
            }
        }

        float s = ((acc[0] + acc[1]) + (acc[2] + acc[3])) +
                  ((acc[4] + acc[5]) + (acc[6] + acc[7]));
        if      (type == 0) abb += (double)s;
        else if (type == 1) att += (double)s;
        else                abt += (double)s;

        buf ^= 1u;
        t = (int)__shfl_sync(FULLMASK, tnext, 0);
    }

    // ---- CTA-level reduction, then 3 atomics per CTA ----
    __syncthreads();
    block_reduce_add(abb, &g_sum[0], sred, tid);
    block_reduce_add(att, &g_sum[1], sred, tid);
    block_reduce_add(abt, &g_sum[2], sred, tid);

    // ---- finalize + full state reset (last CTA) ----
    if (tid == 0) {
        __threadfence();
        unsigned int d = atomicAdd(&g_done, 1u);
        if (d == (unsigned int)(GRID - 1)) {
            double sbb = atomicAdd(&g_sum[0], 0.0);
            double stt = atomicAdd(&g_sum[1], 0.0);
            double sbt = atomicAdd(&g_sum[2], 0.0);
            double inv = 1.0 / ((double)NPTS * (double)NPTS);
            out[0] = (float)((sbb + stt - 2.0 * sbt) * inv);
            g_sum[0] = 0.0; g_sum[1] = 0.0; g_sum[2] = 0.0;
            g_mean[0] = 0.0; g_mean[1] = 0.0;
            g_task = 0u; g_done = 0u;
            g_barZ = 0u; g_barB = 0u; g_barE = 0u; g_barDel = 0u;
            g_flagC = 0u; g_flagDel = 0u; g_flagT = 0u;
            __threadfence();
        }
    }
}

// ---------------------------------------------------------------------------
extern "C" void kernel_launch(void* const* d_in, const int* in_sizes, int n_in,
                              void* d_out, int out_size) {
    const float* base = (const float*)d_in[0];
    const float* tgt  = (const float*)d_in[1];
    const float* lsig = (const float*)d_in[2];
    const float* lsc  = (const float*)d_in[3];

    k_fused<<<GRID, THREADS>>>(base, tgt, lsig, lsc, (float*)d_out);
}